// round 12
// baseline (speedup 1.0000x reference)
#include <cuda_runtime.h>
#include <cstdint>

// Gini of n=8192 fp32 vector, single fused launch.
//
// Key identity: sum over a SORTED column strip c_0<=...<=c_{S-1} with
// prefix sums P and p = #{c < r}:
//    sum_c |r - c| = r*(2p - S) + T - 2*P[p]      (exact; ties give 0)
// So each block: bitonic-sort its 128-col strip in smem (28 phases),
// warp-scan prefix sums, then each row costs a 7-step binary search.
// ~6x fewer hot-path instructions than brute-force pairwise.
//
// 16x16 triangular tiling (136 tiles of 512x512, off-diag weighted 2x),
// 4 column strips of 128 per tile => 544 pair blocks + 1 min/sum block.
// Last-done block reduces partials and emits the closed-form Gini.

#define T_CHUNKS 16
#define CHUNK    512
#define STRIPS   4
#define SCOLS    128
#define NTILES   (T_CHUNKS * (T_CHUNKS + 1) / 2)  // 136
#define NPAIRBLK (NTILES * STRIPS)                // 544
#define THREADS  256
#define GEN_MAX  4096

__device__ float        g_part[NPAIRBLK > GEN_MAX ? NPAIRBLK : GEN_MAX];
__device__ float        g_min_val;
__device__ float        g_sum_val;
__device__ unsigned int g_count = 0;

__device__ __forceinline__ float warp_sum(float v) {
#pragma unroll
    for (int off = 16; off > 0; off >>= 1)
        v += __shfl_xor_sync(0xFFFFFFFFu, v, off);
    return v;
}
__device__ __forceinline__ float warp_min(float v) {
#pragma unroll
    for (int off = 16; off > 0; off >>= 1)
        v = fminf(v, __shfl_xor_sync(0xFFFFFFFFu, v, off));
    return v;
}

// fixed-order reduce of nblk partials + closed form; resets counter
__device__ __forceinline__ void finalize_last(int n, float* __restrict__ out,
                                              int nblk, float* red) {
    const int tid = threadIdx.x;
    float s = 0.0f;
    for (int i = tid; i < nblk; i += THREADS) s += g_part[i];
    s = warp_sum(s);
    if ((tid & 31) == 0) red[tid >> 5] = s;
    __syncthreads();
    if (tid == 0) {
        float S = 0.0f;
#pragma unroll
        for (int w = 0; w < THREADS / 32; ++w) S += red[w];
        const float nf = (float)n;
        float mean = g_sum_val / nf;
        float mn = g_min_val;
        if (mn < 0.0f) mean -= mn;                 // mean(x - min)
        out[0] = S / (2.0f * nf * nf * (mean + 1e-8f));
        g_count = 0;                               // reset for graph replay
    }
}

// ---------------- fused kernel (n == 8192 path) ----------------
__global__ __launch_bounds__(THREADS)
void k_gini(const float* __restrict__ x, float* __restrict__ out, int n) {
    __shared__ __align__(16) float ss[SCOLS];      // sorted strip
    __shared__ float sp[SCOLS + 1];                // exclusive prefix sums
    __shared__ float red[THREADS / 32];
    __shared__ float smins[THREADS / 32];
    __shared__ unsigned int isLast;

    const int tid = threadIdx.x;
    const int b   = blockIdx.x;

    if (b == 0) {
        // -------- min + sum block (overlaps with pairwise blocks) --------
        float mn = 3.402823466e38f, sm = 0.0f;
        const int nv4 = n / 4;
        for (int i = tid; i < nv4; i += THREADS) {
            float4 v = reinterpret_cast<const float4*>(x)[i];
            mn = fminf(mn, fminf(fminf(v.x, v.y), fminf(v.z, v.w)));
            sm += (v.x + v.y) + (v.z + v.w);
        }
        sm = warp_sum(sm);
        mn = warp_min(mn);
        if ((tid & 31) == 0) { red[tid >> 5] = sm; smins[tid >> 5] = mn; }
        __syncthreads();
        if (tid == 0) {
            float S = 0.0f, M = 3.402823466e38f;
#pragma unroll
            for (int w = 0; w < THREADS / 32; ++w) { S += red[w]; M = fminf(M, smins[w]); }
            g_min_val = M;
            g_sum_val = S;
            __threadfence();
            unsigned int c = atomicAdd(&g_count, 1u);
            isLast = (c == gridDim.x - 1) ? 1u : 0u;
        }
        __syncthreads();
        if (isLast) { __threadfence(); finalize_last(n, out, NPAIRBLK, red); }
        return;
    }

    // -------- pairwise tile strip (sorted-strip closed form) --------
    const int t     = b - 1;
    const int strip = t & (STRIPS - 1);
    int rc = 0, rem = t >> 2;                      // tile -> (rc, cc), rc <= cc
    while (rem >= T_CHUNKS - rc) { rem -= (T_CHUNKS - rc); rc++; }
    const int cc = rc + rem;
    const int colBase = cc * CHUNK + strip * SCOLS;
    const int rowBase = rc * CHUNK;

    // load strip + rows (rows early to overlap latency)
    if (tid < SCOLS) ss[tid] = x[colBase + tid];
    const float r0 = x[rowBase + tid];
    const float r1 = x[rowBase + THREADS + tid];
    __syncthreads();

    // bitonic sort of 128 floats (ascending), 28 phases
    for (int k = 2; k <= SCOLS; k <<= 1) {
        for (int j = k >> 1; j > 0; j >>= 1) {
            if (tid < SCOLS) {
                int ixj = tid ^ j;
                if (ixj > tid) {
                    float a = ss[tid];
                    float c = ss[ixj];
                    bool asc = ((tid & k) == 0);
                    if ((a > c) == asc) { ss[tid] = c; ss[ixj] = a; }
                }
            }
            __syncthreads();
        }
    }

    // warp 0: exclusive prefix sums of sorted strip (4 elems/lane + shfl scan)
    if (tid < 32) {
        float4 v = reinterpret_cast<const float4*>(ss)[tid];
        float i0 = v.x;
        float i1 = i0 + v.y;
        float i2 = i1 + v.z;
        float i3 = i2 + v.w;
        float e = i3;
#pragma unroll
        for (int off = 1; off < 32; off <<= 1) {
            float o = __shfl_up_sync(0xFFFFFFFFu, e, off);
            if (tid >= off) e += o;
        }
        float exc = e - i3;                        // exclusive scan of lane totals
        sp[4 * tid]     = exc;
        sp[4 * tid + 1] = exc + i0;
        sp[4 * tid + 2] = exc + i1;
        sp[4 * tid + 3] = exc + i2;
        if (tid == 31) sp[SCOLS] = exc + i3;       // total T
    }
    __syncthreads();

    const float T = sp[SCOLS];

    // two interleaved branchless binary searches (lower_bound, p = #{c < r})
    int lo0 = 0, hi0 = SCOLS, lo1 = 0, hi1 = SCOLS;
#pragma unroll
    for (int it = 0; it < 7; ++it) {
        int m0 = (lo0 + hi0) >> 1;
        int m1 = (lo1 + hi1) >> 1;
        bool lt0 = ss[m0] < r0;
        bool lt1 = ss[m1] < r1;
        lo0 = lt0 ? m0 + 1 : lo0;
        hi0 = lt0 ? hi0 : m0;
        lo1 = lt1 ? m1 + 1 : lo1;
        hi1 = lt1 ? hi1 : m1;
    }
    float mysum = r0 * (float)(2 * lo0 - SCOLS) + (T - 2.0f * sp[lo0])
                + r1 * (float)(2 * lo1 - SCOLS) + (T - 2.0f * sp[lo1]);

    mysum = warp_sum(mysum);
    if ((tid & 31) == 0) red[tid >> 5] = mysum;
    __syncthreads();
    if (tid == 0) {
        float p = 0.0f;
#pragma unroll
        for (int w = 0; w < THREADS / 32; ++w) p += red[w];
        if (rc != cc) p *= 2.0f;                   // symmetry weight
        g_part[t] = p;
        __threadfence();
        unsigned int c = atomicAdd(&g_count, 1u);
        isLast = (c == gridDim.x - 1) ? 1u : 0u;
    }
    __syncthreads();
    if (isLast) { __threadfence(); finalize_last(n, out, NPAIRBLK, red); }
}

// ---------------- generic fallback (any n) ----------------
__global__ void k_gini_generic(const float* __restrict__ x, float* __restrict__ out, int n) {
    __shared__ float red[THREADS];
    __shared__ float smin[THREADS];
    __shared__ unsigned int isLast;
    const int tid = threadIdx.x;
    const int i = blockIdx.x * THREADS + tid;
    float a = 0.0f;
    if (i < n) {
        const float xi = x[i];
        for (int j = 0; j < n; ++j) a += fabsf(xi - x[j]);
    }
    red[tid] = a;
    __syncthreads();
    for (int off = THREADS / 2; off > 0; off >>= 1) {
        if (tid < off) red[tid] += red[tid + off];
        __syncthreads();
    }
    if (tid == 0) {
        g_part[blockIdx.x] = red[0];
        __threadfence();
        unsigned int c = atomicAdd(&g_count, 1u);
        isLast = (c == gridDim.x - 1) ? 1u : 0u;
    }
    __syncthreads();
    if (isLast) {
        __threadfence();
        float mn = 3.402823466e38f, sm = 0.0f;
        for (int k = tid; k < n; k += THREADS) {
            float v = x[k];
            mn = fminf(mn, v);
            sm += v;
        }
        red[tid] = sm; smin[tid] = mn;
        __syncthreads();
        for (int off = THREADS / 2; off > 0; off >>= 1) {
            if (tid < off) {
                red[tid] += red[tid + off];
                smin[tid] = fminf(smin[tid], smin[tid + off]);
            }
            __syncthreads();
        }
        if (tid == 0) { g_min_val = smin[0]; g_sum_val = red[0]; }
        __syncthreads();
        float s = 0.0f;
        for (int k = tid; k < gridDim.x; k += THREADS) s += g_part[k];
        red[tid] = s;
        __syncthreads();
        for (int off = THREADS / 2; off > 0; off >>= 1) {
            if (tid < off) red[tid] += red[tid + off];
            __syncthreads();
        }
        if (tid == 0) {
            const float nf = (float)n;
            float mean = g_sum_val / nf;
            if (g_min_val < 0.0f) mean -= g_min_val;
            out[0] = red[0] / (2.0f * nf * nf * (mean + 1e-8f));
            g_count = 0;
        }
    }
}

extern "C" void kernel_launch(void* const* d_in, const int* in_sizes, int n_in,
                              void* d_out, int out_size) {
    const float* x = (const float*)d_in[0];
    float* out = (float*)d_out;
    const int n = in_sizes[0];

    if (n == T_CHUNKS * CHUNK) {
        k_gini<<<NPAIRBLK + 1, THREADS>>>(x, out, n);
    } else {
        int nblk = (n + THREADS - 1) / THREADS;
        if (nblk > GEN_MAX) nblk = GEN_MAX;
        k_gini_generic<<<nblk, THREADS>>>(x, out, n);
    }
}